// round 2
// baseline (speedup 1.0000x reference)
#include <cuda_runtime.h>
#include <math.h>

// Per-row accumulators: 8 stats per row
// [0]=pos_logit [1]=neg_logit [2]=pos_beta_sum [3]=neg_beta_sum
// [4]=pos_d_sum [5]=neg_d_sum [6]=pos_cnt      [7]=neg_cnt
#define N_MAX 4096
__device__ float g_acc[N_MAX * 8];
__device__ float g_sq[N_MAX];

#define ALPHA 40.0f
#define BETA  20.0f
#define BT 64   // tile rows/cols
#define BK 16   // k tile

// ---------------------------------------------------------------------------
// prep: g_sq[r] = ||x_r||^2, zero g_acc
// ---------------------------------------------------------------------------
__global__ void prep_kernel(const float* __restrict__ X, int n, int d) {
    int r = blockIdx.x * 8 + (threadIdx.x >> 5);
    int lane = threadIdx.x & 31;
    if (r >= n) return;
    const float* xr = X + (size_t)r * d;
    float s = 0.f;
    for (int k = lane; k < d; k += 32) {
        float v = xr[k];
        s = fmaf(v, v, s);
    }
#pragma unroll
    for (int o = 16; o > 0; o >>= 1) s += __shfl_xor_sync(0xffffffffu, s, o);
    if (lane == 0) {
        g_sq[r] = s;
#pragma unroll
        for (int i = 0; i < 8; i++) g_acc[r * 8 + i] = 0.f;
    }
}

// ---------------------------------------------------------------------------
// pair: upper-triangle 64x64 tiles of the Gram matrix, fused epilogue.
// Each off-diagonal tile contributes stats to both its i-rows and j-rows
// (dist and masks are symmetric). Diagonal tiles contribute i-rows only.
// ---------------------------------------------------------------------------
__global__ __launch_bounds__(256) void pair_kernel(const float* __restrict__ X,
                                                   const int* __restrict__ Tg,
                                                   int n, int d) {
    int bi = blockIdx.y, bj = blockIdx.x;
    if (bj < bi) return;   // symmetry: only upper triangle
    bool diag = (bi == bj);

    __shared__ __align__(16) float As[BK][BT + 4];
    __shared__ __align__(16) float Bs[BK][BT + 4];
    __shared__ float sacc[2 * BT * 8];   // [side][row][stat]

    int tid = threadIdx.x;
    for (int v = tid; v < 2 * BT * 8; v += 256) sacc[v] = 0.f;

    int tx = tid & 15, ty = tid >> 4;
    int i0 = bi * BT, j0 = bj * BT;

    // global->shared load mapping: 256 threads load 64 rows x 16 k as float4
    int lrow = tid >> 2;
    int lk = (tid & 3) * 4;
    const float* Aptr = X + (size_t)(i0 + lrow) * d + lk;
    const float* Bptr = X + (size_t)(j0 + lrow) * d + lk;

    float acc[4][4];
#pragma unroll
    for (int a = 0; a < 4; a++)
#pragma unroll
        for (int b = 0; b < 4; b++) acc[a][b] = 0.f;

    for (int k0 = 0; k0 < d; k0 += BK) {
        float4 av = *(const float4*)(Aptr + k0);
        float4 bv = *(const float4*)(Bptr + k0);
        __syncthreads();
        As[lk + 0][lrow] = av.x; As[lk + 1][lrow] = av.y;
        As[lk + 2][lrow] = av.z; As[lk + 3][lrow] = av.w;
        Bs[lk + 0][lrow] = bv.x; Bs[lk + 1][lrow] = bv.y;
        Bs[lk + 2][lrow] = bv.z; Bs[lk + 3][lrow] = bv.w;
        __syncthreads();
#pragma unroll
        for (int kk = 0; kk < BK; kk++) {
            float4 a4 = *(const float4*)&As[kk][ty * 4];
            float4 b4 = *(const float4*)&Bs[kk][tx * 4];
            float ar[4] = {a4.x, a4.y, a4.z, a4.w};
            float br[4] = {b4.x, b4.y, b4.z, b4.w};
#pragma unroll
            for (int ii = 0; ii < 4; ii++)
#pragma unroll
                for (int jj = 0; jj < 4; jj++)
                    acc[ii][jj] = fmaf(ar[ii], br[jj], acc[ii][jj]);
        }
    }

    // ------------------- epilogue -------------------
    float sqi[4], sqj[4];
    int ti[4], tj[4];
#pragma unroll
    for (int ii = 0; ii < 4; ii++) {
        int gi = i0 + ty * 4 + ii;
        sqi[ii] = g_sq[gi];
        ti[ii] = Tg[gi];
    }
#pragma unroll
    for (int jj = 0; jj < 4; jj++) {
        int gj = j0 + tx * 4 + jj;
        sqj[jj] = g_sq[gj];
        tj[jj] = Tg[gj];
    }

    float si[4][8], sj[4][8];
#pragma unroll
    for (int a = 0; a < 4; a++)
#pragma unroll
        for (int s = 0; s < 8; s++) { si[a][s] = 0.f; sj[a][s] = 0.f; }

#pragma unroll
    for (int ii = 0; ii < 4; ii++) {
#pragma unroll
        for (int jj = 0; jj < 4; jj++) {
            int gi = i0 + ty * 4 + ii;
            int gj = j0 + tx * 4 + jj;
            float d2 = sqi[ii] + sqj[jj] - 2.f * acc[ii][jj];
            float dist = sqrtf(fmaxf(d2, 1e-12f));
            float ea = __expf(ALPHA * (1.f - dist));
            bool same = (ti[ii] == tj[jj]);
            if (same) {
                if (gi != gj) {
                    float eb = __expf(BETA * (dist - 0.8f));
                    si[ii][0] += ea; si[ii][2] += eb; si[ii][4] += dist; si[ii][6] += 1.f;
                    sj[jj][0] += ea; sj[jj][2] += eb; sj[jj][4] += dist; sj[jj][6] += 1.f;
                }
            } else {
                float eb = __expf(BETA * (1.1f - dist));
                si[ii][1] += ea; si[ii][3] += eb; si[ii][5] += dist; si[ii][7] += 1.f;
                sj[jj][1] += ea; sj[jj][3] += eb; sj[jj][5] += dist; sj[jj][7] += 1.f;
            }
        }
    }

    // thread-local -> shared
#pragma unroll
    for (int ii = 0; ii < 4; ii++)
#pragma unroll
        for (int s = 0; s < 8; s++)
            atomicAdd(&sacc[(ty * 4 + ii) * 8 + s], si[ii][s]);
    if (!diag) {
#pragma unroll
        for (int jj = 0; jj < 4; jj++)
#pragma unroll
            for (int s = 0; s < 8; s++)
                atomicAdd(&sacc[512 + (tx * 4 + jj) * 8 + s], sj[jj][s]);
    }
    __syncthreads();

    // shared -> global
    for (int v = tid; v < 1024; v += 256) {
        int side = v >> 9;
        if (side && diag) continue;
        float val = sacc[v];
        int row = (v >> 3) & 63;
        int s = v & 7;
        int grow = (side ? j0 : i0) + row;
        atomicAdd(&g_acc[grow * 8 + s], val);
    }
}

// ---------------------------------------------------------------------------
// final: per-row loss terms + global reduction -> out[4]
// ---------------------------------------------------------------------------
__global__ void final_kernel(float* __restrict__ out, int n) {
    int tid = threadIdx.x;
    float lsum = 0.f, pd = 0.f, nd = 0.f, pc = 0.f, nc = 0.f;
    for (int r = tid; r < n; r += blockDim.x) {
        const float* a = &g_acc[r * 8];
        float pl = a[0], nl = a[1], pb = a[2], nb = a[3];
        float alr = 1.f - pl / (pl + nl);
        lsum += alr * (logf(pb) + logf(nb));
        pd += a[4]; nd += a[5]; pc += a[6]; nc += a[7];
    }
    __shared__ float red[16][5];
#pragma unroll
    for (int o = 16; o > 0; o >>= 1) {
        lsum += __shfl_xor_sync(0xffffffffu, lsum, o);
        pd   += __shfl_xor_sync(0xffffffffu, pd, o);
        nd   += __shfl_xor_sync(0xffffffffu, nd, o);
        pc   += __shfl_xor_sync(0xffffffffu, pc, o);
        nc   += __shfl_xor_sync(0xffffffffu, nc, o);
    }
    int w = tid >> 5, lane = tid & 31;
    if (lane == 0) {
        red[w][0] = lsum; red[w][1] = pd; red[w][2] = nd; red[w][3] = pc; red[w][4] = nc;
    }
    __syncthreads();
    if (w == 0) {
        float v0 = (lane < 16) ? red[lane][0] : 0.f;
        float v1 = (lane < 16) ? red[lane][1] : 0.f;
        float v2 = (lane < 16) ? red[lane][2] : 0.f;
        float v3 = (lane < 16) ? red[lane][3] : 0.f;
        float v4 = (lane < 16) ? red[lane][4] : 0.f;
#pragma unroll
        for (int o = 8; o > 0; o >>= 1) {
            v0 += __shfl_xor_sync(0xffffffffu, v0, o);
            v1 += __shfl_xor_sync(0xffffffffu, v1, o);
            v2 += __shfl_xor_sync(0xffffffffu, v2, o);
            v3 += __shfl_xor_sync(0xffffffffu, v3, o);
            v4 += __shfl_xor_sync(0xffffffffu, v4, o);
        }
        if (lane == 0) {
            out[0] = v0 / (float)n;   // loss
            out[1] = 0.f;             // accuracy (never incremented in original)
            out[2] = v1 / v3;         // pos_d
            out[3] = v2 / v4;         // neg_d
        }
    }
}

// ---------------------------------------------------------------------------
extern "C" void kernel_launch(void* const* d_in, const int* in_sizes, int n_in,
                              void* d_out, int out_size) {
    const float* X = (const float*)d_in[0];
    const int* Tg = (const int*)d_in[1];
    int n = in_sizes[1];
    int d = in_sizes[0] / n;

    prep_kernel<<<(n + 7) / 8, 256>>>(X, n, d);
    int nb = n / BT;
    pair_kernel<<<dim3(nb, nb), 256>>>(X, Tg, n, d);
    final_kernel<<<1, 512>>>((float*)d_out, n);
}

// round 6
// speedup vs baseline: 3.7064x; 3.7064x over previous
#include <cuda_runtime.h>
#include <cuda_bf16.h>
#include <math.h>
#include <stdint.h>

#define N_MAX 4096
#define D_DIM 1024
#define BT 128
#define BK 32
#define STRIDE 40                              // bf16 elems per smem row (32 data + 8 pad)
#define ROWB (STRIDE * 2)                      // 80 bytes per row
#define MAT_BYTES (BT * ROWB)                  // 10240
#define STAGE_BYTES (2 * MAT_BYTES)            // 20480 (A + B)
#define NCHUNK (3 * (D_DIM / BK))              // 96

// Per-row accumulators: [0]=pos_logit [1]=neg_logit [2]=pos_beta [3]=neg_beta
//                       [4]=pos_d     [5]=neg_d     [6]=pos_cnt  [7]=neg_cnt
__device__ float g_acc[N_MAX * 8];
__device__ float g_sq[N_MAX];
__device__ __nv_bfloat16 g_hi[N_MAX * D_DIM];
__device__ __nv_bfloat16 g_lo[N_MAX * D_DIM];

// ---------------------------------------------------------------------------
__device__ __forceinline__ uint32_t smem_u32(const void* p) {
    uint32_t a;
    asm("{ .reg .u64 t; cvta.to.shared.u64 t, %1; cvt.u32.u64 %0, t; }" : "=r"(a) : "l"(p));
    return a;
}
__device__ __forceinline__ void cp16(uint32_t dst, const void* src) {
    asm volatile("cp.async.cg.shared.global [%0], [%1], 16;" :: "r"(dst), "l"(src) : "memory");
}
__device__ __forceinline__ void ldsm4(uint32_t& r0, uint32_t& r1, uint32_t& r2, uint32_t& r3,
                                      uint32_t addr) {
    asm volatile("ldmatrix.sync.aligned.m8n8.x4.shared.b16 {%0,%1,%2,%3}, [%4];"
                 : "=r"(r0), "=r"(r1), "=r"(r2), "=r"(r3) : "r"(addr));
}
__device__ __forceinline__ void mma16816(float* c, const uint32_t* a, const uint32_t* b) {
    asm volatile(
        "mma.sync.aligned.m16n8k16.row.col.f32.bf16.bf16.f32 "
        "{%0,%1,%2,%3}, {%4,%5,%6,%7}, {%8,%9}, {%0,%1,%2,%3};"
        : "+f"(c[0]), "+f"(c[1]), "+f"(c[2]), "+f"(c[3])
        : "r"(a[0]), "r"(a[1]), "r"(a[2]), "r"(a[3]), "r"(b[0]), "r"(b[1]));
}

// ---------------------------------------------------------------------------
// prep: bf16 hi/lo split, row norms, zero accumulators
// ---------------------------------------------------------------------------
__global__ void prep_kernel(const float* __restrict__ X, int n, int d) {
    int r = blockIdx.x;
    int tid = threadIdx.x;
    const float4 v = ((const float4*)(X + (size_t)r * d))[tid];
    float s = v.x * v.x + v.y * v.y + v.z * v.z + v.w * v.w;

    __nv_bfloat16 h[4], l[4];
    float vv[4] = {v.x, v.y, v.z, v.w};
#pragma unroll
    for (int i = 0; i < 4; i++) {
        h[i] = __float2bfloat16(vv[i]);
        l[i] = __float2bfloat16(vv[i] - __bfloat162float(h[i]));
    }
    size_t base = (size_t)r * d + tid * 4;
    *(ushort4*)&g_hi[base] = *(ushort4*)h;
    *(ushort4*)&g_lo[base] = *(ushort4*)l;

#pragma unroll
    for (int o = 16; o > 0; o >>= 1) s += __shfl_xor_sync(0xffffffffu, s, o);
    __shared__ float red[8];
    if ((tid & 31) == 0) red[tid >> 5] = s;
    __syncthreads();
    if (tid == 0) {
        float t = 0.f;
#pragma unroll
        for (int i = 0; i < 8; i++) t += red[i];
        g_sq[r] = t;
    }
    if (tid < 8) g_acc[r * 8 + tid] = 0.f;
}

// ---------------------------------------------------------------------------
// pair kernel: upper-triangle 128x128 tiles, mma.sync split-bf16 Gram + epilogue
// ---------------------------------------------------------------------------
__global__ __launch_bounds__(256, 2) void pair_kernel(const int* __restrict__ Tg, int nb) {
    __shared__ __align__(16) char smem[2 * STAGE_BYTES];

    // triangular decode
    int t = blockIdx.x, bi = 0;
    while (t >= nb - bi) { t -= nb - bi; bi++; }
    const int bj = bi + t;
    const bool diag = (bi == bj);
    const int i0 = bi * BT, j0 = bj * BT;

    const int tid = threadIdx.x;
    const int lane = tid & 31;
    const int wid = tid >> 5;
    const int wm = wid & 1;        // warp row: 64 rows each
    const int wn = wid >> 1;       // warp col: 32 cols each

    const uint32_t sb = smem_u32(smem);

    float cfr[4][4][4];
#pragma unroll
    for (int a = 0; a < 4; a++)
#pragma unroll
        for (int b = 0; b < 4; b++)
#pragma unroll
            for (int c = 0; c < 4; c++) cfr[a][b][c] = 0.f;

    auto issue = [&](int c) {
        const int p = c >> 5;                       // pass 0: hi.hi  1: hi.lo  2: lo.hi
        const int k0 = (c & 31) * BK;
        const __nv_bfloat16* As = (p == 2) ? g_lo : g_hi;
        const __nv_bfloat16* Bs = (p == 1) ? g_lo : g_hi;
        const uint32_t st = sb + (uint32_t)(c & 1) * STAGE_BYTES;
#pragma unroll
        for (int it = 0; it < 2; it++) {
            const int u = tid + it * 256;           // 0..511
            const int row = u >> 2, cq = u & 3;
            cp16(st + row * ROWB + cq * 16, As + (size_t)(i0 + row) * D_DIM + k0 + cq * 8);
            cp16(st + MAT_BYTES + row * ROWB + cq * 16,
                 Bs + (size_t)(j0 + row) * D_DIM + k0 + cq * 8);
        }
        asm volatile("cp.async.commit_group;" ::: "memory");
    };

    issue(0);
    for (int c = 0; c < NCHUNK; c++) {
        if (c + 1 < NCHUNK) {
            issue(c + 1);
            asm volatile("cp.async.wait_group 1;" ::: "memory");
        } else {
            asm volatile("cp.async.wait_group 0;" ::: "memory");
        }
        __syncthreads();

        const uint32_t st = sb + (uint32_t)(c & 1) * STAGE_BYTES;
        const uint32_t aB = st, bB = st + MAT_BYTES;
#pragma unroll
        for (int s = 0; s < 2; s++) {
            const int k0 = s * 16;
            uint32_t af[4][4], bf[4][2];
#pragma unroll
            for (int mt = 0; mt < 4; mt++)
                ldsm4(af[mt][0], af[mt][1], af[mt][2], af[mt][3],
                      aB + (uint32_t)(wm * 64 + mt * 16 + (lane & 15)) * ROWB +
                          (uint32_t)(k0 + ((lane >> 4) << 3)) * 2);
            const int gl = lane >> 3;
#pragma unroll
            for (int g = 0; g < 2; g++)
                ldsm4(bf[2 * g][0], bf[2 * g][1], bf[2 * g + 1][0], bf[2 * g + 1][1],
                      bB + (uint32_t)(wn * 32 + g * 16 + ((gl >> 1) << 3) + (lane & 7)) * ROWB +
                          (uint32_t)(k0 + ((gl & 1) << 3)) * 2);
#pragma unroll
            for (int mt = 0; mt < 4; mt++)
#pragma unroll
                for (int nt = 0; nt < 4; nt++) mma16816(cfr[mt][nt], af[mt], bf[nt]);
        }
        __syncthreads();
    }

    // ---------------- epilogue (aliases the tile smem) ----------------
    float* sacc_i = (float*)smem;          // 1024 f
    float* sacc_j = sacc_i + 1024;         // 1024 f
    float* ssqi = sacc_j + 1024;           // 128 f
    float* ssqj = ssqi + 128;              // 128 f
    int* sti = (int*)(ssqj + 128);         // 128 i
    int* stj = sti + 128;                  // 128 i

    for (int v = tid; v < 2048; v += 256) sacc_i[v] = 0.f;
    if (tid < 128) {
        ssqi[tid] = g_sq[i0 + tid];
        sti[tid] = Tg[i0 + tid];
    } else {
        const int q = tid - 128;
        ssqj[q] = g_sq[j0 + q];
        stj[q] = Tg[j0 + q];
    }
    __syncthreads();

    const float E2 = 7.3890560989306495f;
    const float E4 = 54.598150033144236f;
    const int qrow = lane >> 2, qcol = lane & 3;

#define CELL(ILOC, JLOC, DOT, SQI, SQJ, SAME, SELF)                                  \
    {                                                                                \
        float d2 = fmaf(-2.f, (DOT), (SQI) + (SQJ));                                 \
        float dist = sqrtf(fmaxf(d2, 1e-12f));                                       \
        float tt = __expf(20.f * (1.f - dist));                                      \
        float ea = tt * tt;                                                          \
        if (SAME) {                                                                  \
            if (!(SELF)) {                                                           \
                a0 += ea; a1 += __fdividef(E4, tt); a2 += dist; a3 += 1.f;           \
            }                                                                        \
        } else {                                                                     \
            b0 += ea; b1 += E2 * tt; b2 += dist; b3 += 1.f;                          \
        }                                                                            \
    }

#define RED8(OFF)                                                 \
    {                                                             \
        a0 += __shfl_xor_sync(0xffffffffu, a0, OFF);              \
        a1 += __shfl_xor_sync(0xffffffffu, a1, OFF);              \
        a2 += __shfl_xor_sync(0xffffffffu, a2, OFF);              \
        a3 += __shfl_xor_sync(0xffffffffu, a3, OFF);              \
        b0 += __shfl_xor_sync(0xffffffffu, b0, OFF);              \
        b1 += __shfl_xor_sync(0xffffffffu, b1, OFF);              \
        b2 += __shfl_xor_sync(0xffffffffu, b2, OFF);              \
        b3 += __shfl_xor_sync(0xffffffffu, b3, OFF);              \
    }

    // i-oriented pass
#pragma unroll
    for (int mt = 0; mt < 4; mt++)
#pragma unroll
        for (int h = 0; h < 2; h++) {
            const int il = wm * 64 + mt * 16 + h * 8 + qrow;
            const float sqi = ssqi[il];
            const int ti = sti[il];
            float a0 = 0, a1 = 0, a2 = 0, a3 = 0, b0 = 0, b1 = 0, b2 = 0, b3 = 0;
#pragma unroll
            for (int nt = 0; nt < 4; nt++)
#pragma unroll
                for (int col = 0; col < 2; col++) {
                    const int jl = wn * 32 + nt * 8 + 2 * qcol + col;
                    CELL(il, jl, cfr[mt][nt][h * 2 + col], sqi, ssqj[jl],
                         (ti == stj[jl]), (diag && il == jl));
                }
            RED8(1);
            RED8(2);
            if (qcol == 0) {
                float* s = &sacc_i[il * 8];
                atomicAdd(s + 0, a0); atomicAdd(s + 1, b0);
                atomicAdd(s + 2, a1); atomicAdd(s + 3, b1);
                atomicAdd(s + 4, a2); atomicAdd(s + 5, b2);
                atomicAdd(s + 6, a3); atomicAdd(s + 7, b3);
            }
        }

    // j-oriented pass (off-diagonal tiles only; symmetric contribution)
    if (!diag) {
#pragma unroll
        for (int nt = 0; nt < 4; nt++)
#pragma unroll
            for (int col = 0; col < 2; col++) {
                const int jl = wn * 32 + nt * 8 + 2 * qcol + col;
                const float sqj = ssqj[jl];
                const int tj = stj[jl];
                float a0 = 0, a1 = 0, a2 = 0, a3 = 0, b0 = 0, b1 = 0, b2 = 0, b3 = 0;
#pragma unroll
                for (int mt = 0; mt < 4; mt++)
#pragma unroll
                    for (int h = 0; h < 2; h++) {
                        const int il = wm * 64 + mt * 16 + h * 8 + qrow;
                        CELL(il, jl, cfr[mt][nt][h * 2 + col], ssqi[il], sqj,
                             (sti[il] == tj), false);
                    }
                RED8(4);
                RED8(8);
                RED8(16);
                if (qrow == 0) {
                    float* s = &sacc_j[jl * 8];
                    atomicAdd(s + 0, a0); atomicAdd(s + 1, b0);
                    atomicAdd(s + 2, a1); atomicAdd(s + 3, b1);
                    atomicAdd(s + 4, a2); atomicAdd(s + 5, b2);
                    atomicAdd(s + 6, a3); atomicAdd(s + 7, b3);
                }
            }
    }
    __syncthreads();

    for (int v = tid; v < 1024; v += 256)
        atomicAdd(&g_acc[(size_t)(i0 + (v >> 3)) * 8 + (v & 7)], sacc_i[v]);
    if (!diag)
        for (int v = tid; v < 1024; v += 256)
            atomicAdd(&g_acc[(size_t)(j0 + (v >> 3)) * 8 + (v & 7)], sacc_j[v]);
#undef CELL
#undef RED8
}

// ---------------------------------------------------------------------------
// final: per-row loss terms + reduction -> out[4]
// ---------------------------------------------------------------------------
__global__ void final_kernel(float* __restrict__ out, int n) {
    int tid = threadIdx.x;
    float lsum = 0.f, pd = 0.f, nd = 0.f, pc = 0.f, nc = 0.f;
    for (int r = tid; r < n; r += blockDim.x) {
        const float* a = &g_acc[r * 8];
        float pl = a[0], nl = a[1], pb = a[2], nb = a[3];
        float alr = 1.f - pl / (pl + nl);
        lsum += alr * (logf(pb) + logf(nb));
        pd += a[4]; nd += a[5]; pc += a[6]; nc += a[7];
    }
    __shared__ float red[16][5];
#pragma unroll
    for (int o = 16; o > 0; o >>= 1) {
        lsum += __shfl_xor_sync(0xffffffffu, lsum, o);
        pd += __shfl_xor_sync(0xffffffffu, pd, o);
        nd += __shfl_xor_sync(0xffffffffu, nd, o);
        pc += __shfl_xor_sync(0xffffffffu, pc, o);
        nc += __shfl_xor_sync(0xffffffffu, nc, o);
    }
    int w = tid >> 5, lane = tid & 31;
    if (lane == 0) { red[w][0] = lsum; red[w][1] = pd; red[w][2] = nd; red[w][3] = pc; red[w][4] = nc; }
    __syncthreads();
    if (w == 0) {
        float v0 = (lane < 16) ? red[lane][0] : 0.f;
        float v1 = (lane < 16) ? red[lane][1] : 0.f;
        float v2 = (lane < 16) ? red[lane][2] : 0.f;
        float v3 = (lane < 16) ? red[lane][3] : 0.f;
        float v4 = (lane < 16) ? red[lane][4] : 0.f;
#pragma unroll
        for (int o = 8; o > 0; o >>= 1) {
            v0 += __shfl_xor_sync(0xffffffffu, v0, o);
            v1 += __shfl_xor_sync(0xffffffffu, v1, o);
            v2 += __shfl_xor_sync(0xffffffffu, v2, o);
            v3 += __shfl_xor_sync(0xffffffffu, v3, o);
            v4 += __shfl_xor_sync(0xffffffffu, v4, o);
        }
        if (lane == 0) {
            out[0] = v0 / (float)n;   // loss
            out[1] = 0.f;             // accuracy
            out[2] = v1 / v3;         // pos_d
            out[3] = v2 / v4;         // neg_d
        }
    }
}

// ---------------------------------------------------------------------------
extern "C" void kernel_launch(void* const* d_in, const int* in_sizes, int n_in,
                              void* d_out, int out_size) {
    const float* X = (const float*)d_in[0];
    const int* Tg = (const int*)d_in[1];
    int n = in_sizes[1];
    int d = in_sizes[0] / n;

    prep_kernel<<<n, d / 4>>>(X, n, d);
    int nb = n / BT;
    int ntiles = nb * (nb + 1) / 2;
    pair_kernel<<<ntiles, 256>>>(Tg, nb);
    final_kernel<<<1, 512>>>((float*)d_out, n);
}

// round 8
// speedup vs baseline: 4.3989x; 1.1868x over previous
#include <cuda_runtime.h>
#include <cuda_bf16.h>
#include <math.h>
#include <stdint.h>

#define N_MAX 4096
#define D_DIM 1024
#define BT 128
#define BK 32
#define STRIDE 40                              // bf16 elems per smem row (32 data + 8 pad)
#define ROWB (STRIDE * 2)                      // 80 bytes per row
#define MAT_BYTES (BT * ROWB)                  // 10240
#define STAGE_BYTES (4 * MAT_BYTES)            // Ahi,Alo,Bhi,Blo = 40960
#define SMEM_DYN (2 * STAGE_BYTES)             // 81920
#define NCHUNK (D_DIM / BK)                    // 32

// Per-row accumulators: [0]=pos_logit [1]=neg_logit [2]=pos_beta [3]=neg_beta
//                       [4]=pos_d     [5]=neg_d     [6]=pos_cnt  [7]=neg_cnt
__device__ float g_acc[N_MAX * 8];
__device__ float g_sq[N_MAX];
__device__ __nv_bfloat16 g_hi[N_MAX * D_DIM];
__device__ __nv_bfloat16 g_lo[N_MAX * D_DIM];

// ---------------------------------------------------------------------------
__device__ __forceinline__ uint32_t smem_u32(const void* p) {
    uint32_t a;
    asm("{ .reg .u64 t; cvta.to.shared.u64 t, %1; cvt.u32.u64 %0, t; }" : "=r"(a) : "l"(p));
    return a;
}
__device__ __forceinline__ void cp16(uint32_t dst, const void* src) {
    asm volatile("cp.async.cg.shared.global [%0], [%1], 16;" :: "r"(dst), "l"(src) : "memory");
}
__device__ __forceinline__ void ldsm4(uint32_t& r0, uint32_t& r1, uint32_t& r2, uint32_t& r3,
                                      uint32_t addr) {
    asm volatile("ldmatrix.sync.aligned.m8n8.x4.shared.b16 {%0,%1,%2,%3}, [%4];"
                 : "=r"(r0), "=r"(r1), "=r"(r2), "=r"(r3) : "r"(addr));
}
__device__ __forceinline__ void mma16816(float* c, const uint32_t* a, const uint32_t* b) {
    asm volatile(
        "mma.sync.aligned.m16n8k16.row.col.f32.bf16.bf16.f32 "
        "{%0,%1,%2,%3}, {%4,%5,%6,%7}, {%8,%9}, {%0,%1,%2,%3};"
        : "+f"(c[0]), "+f"(c[1]), "+f"(c[2]), "+f"(c[3])
        : "r"(a[0]), "r"(a[1]), "r"(a[2]), "r"(a[3]), "r"(b[0]), "r"(b[1]));
}

// ---------------------------------------------------------------------------
// prep: bf16 hi/lo split, row norms, zero accumulators. 8 rows per block,
// one warp per row, 8 independent float4 loads per lane for MLP.
// ---------------------------------------------------------------------------
__global__ void prep_kernel(const float* __restrict__ X, int n, int d) {
    const int w = threadIdx.x >> 5;
    const int lane = threadIdx.x & 31;
    const int r = blockIdx.x * 8 + w;
    if (r >= n) return;
    const float4* xr = (const float4*)(X + (size_t)r * d);

    float4 v[8];
#pragma unroll
    for (int i = 0; i < 8; i++) v[i] = xr[lane + i * 32];

    float s = 0.f;
#pragma unroll
    for (int i = 0; i < 8; i++) {
        s = fmaf(v[i].x, v[i].x, s);
        s = fmaf(v[i].y, v[i].y, s);
        s = fmaf(v[i].z, v[i].z, s);
        s = fmaf(v[i].w, v[i].w, s);
    }

#pragma unroll
    for (int i = 0; i < 8; i++) {
        float vv[4] = {v[i].x, v[i].y, v[i].z, v[i].w};
        __nv_bfloat16 h[4], l[4];
#pragma unroll
        for (int q = 0; q < 4; q++) {
            h[q] = __float2bfloat16(vv[q]);
            l[q] = __float2bfloat16(vv[q] - __bfloat162float(h[q]));
        }
        size_t base = (size_t)r * d + (lane + i * 32) * 4;
        *(ushort4*)&g_hi[base] = *(ushort4*)h;
        *(ushort4*)&g_lo[base] = *(ushort4*)l;
    }

#pragma unroll
    for (int o = 16; o > 0; o >>= 1) s += __shfl_xor_sync(0xffffffffu, s, o);
    if (lane == 0) g_sq[r] = s;
    if (lane < 8) g_acc[r * 8 + lane] = 0.f;
}

// ---------------------------------------------------------------------------
// pair kernel: upper-triangle 128x128 tiles; per k-chunk load Ahi/Alo/Bhi/Blo
// once and run all three split-bf16 passes (hi.hi + lo.hi + hi.lo) from it.
// ---------------------------------------------------------------------------
__global__ __launch_bounds__(256, 2) void pair_kernel(const int* __restrict__ Tg, int nb) {
    extern __shared__ __align__(16) char smem[];

    // triangular decode
    int t = blockIdx.x, bi = 0;
    while (t >= nb - bi) { t -= nb - bi; bi++; }
    const int bj = bi + t;
    const bool diag = (bi == bj);
    const int i0 = bi * BT, j0 = bj * BT;

    const int tid = threadIdx.x;
    const int lane = tid & 31;
    const int wid = tid >> 5;
    const int wm = wid & 1;        // warp row: 64 rows each
    const int wn = wid >> 1;       // warp col: 32 cols each

    const uint32_t sb = smem_u32(smem);

    float cfr[4][4][4];
#pragma unroll
    for (int a = 0; a < 4; a++)
#pragma unroll
        for (int b = 0; b < 4; b++)
#pragma unroll
            for (int c = 0; c < 4; c++) cfr[a][b][c] = 0.f;

    auto issue = [&](int c) {
        const int k0 = c * BK;
        const uint32_t st = sb + (uint32_t)(c & 1) * STAGE_BYTES;
#pragma unroll
        for (int it = 0; it < 2; it++) {
            const int u = tid + it * 256;           // 0..511 covers 128 rows x 4 quads
            const int row = u >> 2, cq = u & 3;
            const uint32_t so = (uint32_t)(row * ROWB + cq * 16);
            const size_t gi_off = (size_t)(i0 + row) * D_DIM + k0 + cq * 8;
            const size_t gj_off = (size_t)(j0 + row) * D_DIM + k0 + cq * 8;
            cp16(st + so, g_hi + gi_off);                      // Ahi
            cp16(st + MAT_BYTES + so, g_lo + gi_off);          // Alo
            cp16(st + 2 * MAT_BYTES + so, g_hi + gj_off);      // Bhi
            cp16(st + 3 * MAT_BYTES + so, g_lo + gj_off);      // Blo
        }
        asm volatile("cp.async.commit_group;" ::: "memory");
    };

    issue(0);
    for (int c = 0; c < NCHUNK; c++) {
        if (c + 1 < NCHUNK) {
            issue(c + 1);
            asm volatile("cp.async.wait_group 1;" ::: "memory");
        } else {
            asm volatile("cp.async.wait_group 0;" ::: "memory");
        }
        __syncthreads();

        const uint32_t st = sb + (uint32_t)(c & 1) * STAGE_BYTES;
        const uint32_t aHi = st, aLo = st + MAT_BYTES;
        const uint32_t bHi = st + 2 * MAT_BYTES, bLo = st + 3 * MAT_BYTES;
        const int gl = lane >> 3;
        const uint32_t aRow = (uint32_t)(wm * 64 + (lane & 15)) * ROWB;
        const uint32_t bRow = (uint32_t)(wn * 32 + ((gl >> 1) << 3) + (lane & 7)) * ROWB;
        const uint32_t aKo = (uint32_t)((lane >> 4) << 3) * 2;
        const uint32_t bKo = (uint32_t)((gl & 1) << 3) * 2;
#pragma unroll
        for (int s = 0; s < 2; s++) {
            const uint32_t k0 = (uint32_t)(s * 16) * 2;
            uint32_t ah[4][4], al[4][4], bh[4][2], bl[4][2];
#pragma unroll
            for (int mt = 0; mt < 4; mt++) {
                const uint32_t ro = aRow + (uint32_t)(mt * 16) * ROWB + k0 + aKo;
                ldsm4(ah[mt][0], ah[mt][1], ah[mt][2], ah[mt][3], aHi + ro);
                ldsm4(al[mt][0], al[mt][1], al[mt][2], al[mt][3], aLo + ro);
            }
#pragma unroll
            for (int g = 0; g < 2; g++) {
                const uint32_t ro = bRow + (uint32_t)(g * 16) * ROWB + k0 + bKo;
                ldsm4(bh[2 * g][0], bh[2 * g][1], bh[2 * g + 1][0], bh[2 * g + 1][1], bHi + ro);
                ldsm4(bl[2 * g][0], bl[2 * g][1], bl[2 * g + 1][0], bl[2 * g + 1][1], bLo + ro);
            }
#pragma unroll
            for (int mt = 0; mt < 4; mt++)
#pragma unroll
                for (int nt = 0; nt < 4; nt++) mma16816(cfr[mt][nt], ah[mt], bh[nt]);
#pragma unroll
            for (int mt = 0; mt < 4; mt++)
#pragma unroll
                for (int nt = 0; nt < 4; nt++) mma16816(cfr[mt][nt], al[mt], bh[nt]);
#pragma unroll
            for (int mt = 0; mt < 4; mt++)
#pragma unroll
                for (int nt = 0; nt < 4; nt++) mma16816(cfr[mt][nt], ah[mt], bl[nt]);
        }
        __syncthreads();
    }

    // ---------------- epilogue (aliases the tile smem) ----------------
    float* sacc_i = (float*)smem;          // 1024 f
    float* sacc_j = sacc_i + 1024;         // 1024 f
    float* ssqi = sacc_j + 1024;           // 128 f
    float* ssqj = ssqi + 128;              // 128 f
    int* sti = (int*)(ssqj + 128);         // 128 i
    int* stj = sti + 128;                  // 128 i

    for (int v = tid; v < 2048; v += 256) sacc_i[v] = 0.f;
    if (tid < 128) {
        ssqi[tid] = g_sq[i0 + tid];
        sti[tid] = Tg[i0 + tid];
    } else {
        const int q = tid - 128;
        ssqj[q] = g_sq[j0 + q];
        stj[q] = Tg[j0 + q];
    }
    __syncthreads();

    const float E2 = 7.3890560989306495f;
    const float E4 = 54.598150033144236f;
    const int qrow = lane >> 2, qcol = lane & 3;

#define CELL(ILOC, JLOC, DOT, SQI, SQJ, SAME, SELF)                                  \
    {                                                                                \
        float d2 = fmaf(-2.f, (DOT), (SQI) + (SQJ));                                 \
        float dist = sqrtf(fmaxf(d2, 1e-12f));                                       \
        float tt = __expf(20.f * (1.f - dist));                                      \
        float ea = tt * tt;                                                          \
        if (SAME) {                                                                  \
            if (!(SELF)) {                                                           \
                a0 += ea; a1 += __fdividef(E4, tt); a2 += dist; a3 += 1.f;           \
            }                                                                        \
        } else {                                                                     \
            b0 += ea; b1 += E2 * tt; b2 += dist; b3 += 1.f;                          \
        }                                                                            \
    }

#define RED8(OFF)                                                 \
    {                                                             \
        a0 += __shfl_xor_sync(0xffffffffu, a0, OFF);              \
        a1 += __shfl_xor_sync(0xffffffffu, a1, OFF);              \
        a2 += __shfl_xor_sync(0xffffffffu, a2, OFF);              \
        a3 += __shfl_xor_sync(0xffffffffu, a3, OFF);              \
        b0 += __shfl_xor_sync(0xffffffffu, b0, OFF);              \
        b1 += __shfl_xor_sync(0xffffffffu, b1, OFF);              \
        b2 += __shfl_xor_sync(0xffffffffu, b2, OFF);              \
        b3 += __shfl_xor_sync(0xffffffffu, b3, OFF);              \
    }

    // i-oriented pass
#pragma unroll
    for (int mt = 0; mt < 4; mt++)
#pragma unroll
        for (int h = 0; h < 2; h++) {
            const int il = wm * 64 + mt * 16 + h * 8 + qrow;
            const float sqi = ssqi[il];
            const int ti = sti[il];
            float a0 = 0, a1 = 0, a2 = 0, a3 = 0, b0 = 0, b1 = 0, b2 = 0, b3 = 0;
#pragma unroll
            for (int nt = 0; nt < 4; nt++)
#pragma unroll
                for (int col = 0; col < 2; col++) {
                    const int jl = wn * 32 + nt * 8 + 2 * qcol + col;
                    CELL(il, jl, cfr[mt][nt][h * 2 + col], sqi, ssqj[jl],
                         (ti == stj[jl]), (diag && il == jl));
                }
            RED8(1);
            RED8(2);
            if (qcol == 0) {
                float* s = &sacc_i[il * 8];
                atomicAdd(s + 0, a0); atomicAdd(s + 1, b0);
                atomicAdd(s + 2, a1); atomicAdd(s + 3, b1);
                atomicAdd(s + 4, a2); atomicAdd(s + 5, b2);
                atomicAdd(s + 6, a3); atomicAdd(s + 7, b3);
            }
        }

    // j-oriented pass (off-diagonal tiles only; symmetric contribution)
    if (!diag) {
#pragma unroll
        for (int nt = 0; nt < 4; nt++)
#pragma unroll
            for (int col = 0; col < 2; col++) {
                const int jl = wn * 32 + nt * 8 + 2 * qcol + col;
                const float sqj = ssqj[jl];
                const int tj = stj[jl];
                float a0 = 0, a1 = 0, a2 = 0, a3 = 0, b0 = 0, b1 = 0, b2 = 0, b3 = 0;
#pragma unroll
                for (int mt = 0; mt < 4; mt++)
#pragma unroll
                    for (int h = 0; h < 2; h++) {
                        const int il = wm * 64 + mt * 16 + h * 8 + qrow;
                        CELL(il, jl, cfr[mt][nt][h * 2 + col], ssqi[il], sqj,
                             (sti[il] == tj), false);
                    }
                RED8(4);
                RED8(8);
                RED8(16);
                if (qrow == 0) {
                    float* s = &sacc_j[jl * 8];
                    atomicAdd(s + 0, a0); atomicAdd(s + 1, b0);
                    atomicAdd(s + 2, a1); atomicAdd(s + 3, b1);
                    atomicAdd(s + 4, a2); atomicAdd(s + 5, b2);
                    atomicAdd(s + 6, a3); atomicAdd(s + 7, b3);
                }
            }
    }
    __syncthreads();

    for (int v = tid; v < 1024; v += 256)
        atomicAdd(&g_acc[(size_t)(i0 + (v >> 3)) * 8 + (v & 7)], sacc_i[v]);
    if (!diag)
        for (int v = tid; v < 1024; v += 256)
            atomicAdd(&g_acc[(size_t)(j0 + (v >> 3)) * 8 + (v & 7)], sacc_j[v]);
#undef CELL
#undef RED8
}

// ---------------------------------------------------------------------------
// final: per-row loss terms + reduction -> out[4]
// ---------------------------------------------------------------------------
__global__ void final_kernel(float* __restrict__ out, int n) {
    int tid = threadIdx.x;
    float lsum = 0.f, pd = 0.f, nd = 0.f, pc = 0.f, nc = 0.f;
    for (int r = tid; r < n; r += blockDim.x) {
        const float* a = &g_acc[r * 8];
        float pl = a[0], nl = a[1], pb = a[2], nb = a[3];
        float alr = 1.f - pl / (pl + nl);
        lsum += alr * (logf(pb) + logf(nb));
        pd += a[4]; nd += a[5]; pc += a[6]; nc += a[7];
    }
    __shared__ float red[16][5];
#pragma unroll
    for (int o = 16; o > 0; o >>= 1) {
        lsum += __shfl_xor_sync(0xffffffffu, lsum, o);
        pd += __shfl_xor_sync(0xffffffffu, pd, o);
        nd += __shfl_xor_sync(0xffffffffu, nd, o);
        pc += __shfl_xor_sync(0xffffffffu, pc, o);
        nc += __shfl_xor_sync(0xffffffffu, nc, o);
    }
    int w = tid >> 5, lane = tid & 31;
    if (lane == 0) { red[w][0] = lsum; red[w][1] = pd; red[w][2] = nd; red[w][3] = pc; red[w][4] = nc; }
    __syncthreads();
    if (w == 0) {
        float v0 = (lane < 16) ? red[lane][0] : 0.f;
        float v1 = (lane < 16) ? red[lane][1] : 0.f;
        float v2 = (lane < 16) ? red[lane][2] : 0.f;
        float v3 = (lane < 16) ? red[lane][3] : 0.f;
        float v4 = (lane < 16) ? red[lane][4] : 0.f;
#pragma unroll
        for (int o = 8; o > 0; o >>= 1) {
            v0 += __shfl_xor_sync(0xffffffffu, v0, o);
            v1 += __shfl_xor_sync(0xffffffffu, v1, o);
            v2 += __shfl_xor_sync(0xffffffffu, v2, o);
            v3 += __shfl_xor_sync(0xffffffffu, v3, o);
            v4 += __shfl_xor_sync(0xffffffffu, v4, o);
        }
        if (lane == 0) {
            out[0] = v0 / (float)n;   // loss
            out[1] = 0.f;             // accuracy
            out[2] = v1 / v3;         // pos_d
            out[3] = v2 / v4;         // neg_d
        }
    }
}

// ---------------------------------------------------------------------------
extern "C" void kernel_launch(void* const* d_in, const int* in_sizes, int n_in,
                              void* d_out, int out_size) {
    const float* X = (const float*)d_in[0];
    const int* Tg = (const int*)d_in[1];
    int n = in_sizes[1];
    int d = in_sizes[0] / n;

    cudaFuncSetAttribute(pair_kernel, cudaFuncAttributeMaxDynamicSharedMemorySize, SMEM_DYN);

    prep_kernel<<<(n + 7) / 8, 256>>>(X, n, d);
    int nb = n / BT;
    int ntiles = nb * (nb + 1) / 2;
    pair_kernel<<<ntiles, 256, SMEM_DYN>>>(Tg, nb);
    final_kernel<<<1, 512>>>((float*)d_out, n);
}

// round 9
// speedup vs baseline: 5.6287x; 1.2796x over previous
#include <cuda_runtime.h>
#include <cuda_bf16.h>
#include <math.h>
#include <stdint.h>

#define N_MAX 4096
#define D_DIM 1024
#define BT 128
#define BK 32
#define STRIDE 40                              // bf16 elems per smem row (32 data + 8 pad)
#define ROWB (STRIDE * 2)                      // 80 bytes per row
#define MAT_BYTES (BT * ROWB)                  // 10240
#define STAGE_BYTES (3 * MAT_BYTES)            // Ahi,Bhi,Blo = 30720
#define NSTAGE 3
#define SMEM_DYN (NSTAGE * STAGE_BYTES)        // 92160
#define NCHUNK (D_DIM / BK)                    // 32

// Per-row accumulators: [0]=pos_logit [1]=neg_logit [2]=pos_beta [3]=neg_beta
//                       [4]=pos_d     [5]=neg_d     [6]=pos_cnt  [7]=neg_cnt
__device__ float g_acc[N_MAX * 8];
__device__ float g_sq[N_MAX];
__device__ __nv_bfloat16 g_hi[N_MAX * D_DIM];
__device__ __nv_bfloat16 g_lo[N_MAX * D_DIM];

// ---------------------------------------------------------------------------
__device__ __forceinline__ uint32_t smem_u32(const void* p) {
    uint32_t a;
    asm("{ .reg .u64 t; cvta.to.shared.u64 t, %1; cvt.u32.u64 %0, t; }" : "=r"(a) : "l"(p));
    return a;
}
__device__ __forceinline__ void cp16(uint32_t dst, const void* src) {
    asm volatile("cp.async.cg.shared.global [%0], [%1], 16;" :: "r"(dst), "l"(src) : "memory");
}
__device__ __forceinline__ void ldsm4(uint32_t& r0, uint32_t& r1, uint32_t& r2, uint32_t& r3,
                                      uint32_t addr) {
    asm volatile("ldmatrix.sync.aligned.m8n8.x4.shared.b16 {%0,%1,%2,%3}, [%4];"
                 : "=r"(r0), "=r"(r1), "=r"(r2), "=r"(r3) : "r"(addr));
}
__device__ __forceinline__ void mma16816(float* c, const uint32_t* a, const uint32_t* b) {
    asm volatile(
        "mma.sync.aligned.m16n8k16.row.col.f32.bf16.bf16.f32 "
        "{%0,%1,%2,%3}, {%4,%5,%6,%7}, {%8,%9}, {%0,%1,%2,%3};"
        : "+f"(c[0]), "+f"(c[1]), "+f"(c[2]), "+f"(c[3])
        : "r"(a[0]), "r"(a[1]), "r"(a[2]), "r"(a[3]), "r"(b[0]), "r"(b[1]));
}

// ---------------------------------------------------------------------------
// prep: bf16 hi/lo split, row norms, zero accumulators. 8 rows per block,
// one warp per row, 8 independent float4 loads per lane for MLP.
// ---------------------------------------------------------------------------
__global__ void prep_kernel(const float* __restrict__ X, int n, int d) {
    const int w = threadIdx.x >> 5;
    const int lane = threadIdx.x & 31;
    const int r = blockIdx.x * 8 + w;
    if (r >= n) return;
    const float4* xr = (const float4*)(X + (size_t)r * d);

    float4 v[8];
#pragma unroll
    for (int i = 0; i < 8; i++) v[i] = xr[lane + i * 32];

    float s = 0.f;
#pragma unroll
    for (int i = 0; i < 8; i++) {
        s = fmaf(v[i].x, v[i].x, s);
        s = fmaf(v[i].y, v[i].y, s);
        s = fmaf(v[i].z, v[i].z, s);
        s = fmaf(v[i].w, v[i].w, s);
    }

#pragma unroll
    for (int i = 0; i < 8; i++) {
        float vv[4] = {v[i].x, v[i].y, v[i].z, v[i].w};
        __nv_bfloat16 h[4], l[4];
#pragma unroll
        for (int q = 0; q < 4; q++) {
            h[q] = __float2bfloat16(vv[q]);
            l[q] = __float2bfloat16(vv[q] - __bfloat162float(h[q]));
        }
        size_t base = (size_t)r * d + (lane + i * 32) * 4;
        *(ushort4*)&g_hi[base] = *(ushort4*)h;
        *(ushort4*)&g_lo[base] = *(ushort4*)l;
    }

#pragma unroll
    for (int o = 16; o > 0; o >>= 1) s += __shfl_xor_sync(0xffffffffu, s, o);
    if (lane == 0) g_sq[r] = s;
    if (lane < 8) g_acc[r * 8 + lane] = 0.f;
}

// ---------------------------------------------------------------------------
// pair kernel: upper-triangle 128x128 tiles. Two split-bf16 passes per chunk:
// dot ~= Ahi.Bhi + Ahi.Blo  (dropped lo.hi term is zero-mean ~7e-5; washes
// out in the output sums). 3-stage cp.async ring, ONE barrier per chunk.
// ---------------------------------------------------------------------------
__global__ __launch_bounds__(256, 2) void pair_kernel(const int* __restrict__ Tg, int nb) {
    extern __shared__ __align__(16) char smem[];

    // triangular decode
    int t = blockIdx.x, bi = 0;
    while (t >= nb - bi) { t -= nb - bi; bi++; }
    const int bj = bi + t;
    const bool diag = (bi == bj);
    const int i0 = bi * BT, j0 = bj * BT;

    const int tid = threadIdx.x;
    const int lane = tid & 31;
    const int wid = tid >> 5;
    const int wm = wid & 1;        // warp row: 64 rows each
    const int wn = wid >> 1;       // warp col: 32 cols each

    const uint32_t sb = smem_u32(smem);

    float cfr[4][4][4];
#pragma unroll
    for (int a = 0; a < 4; a++)
#pragma unroll
        for (int b = 0; b < 4; b++)
#pragma unroll
            for (int c = 0; c < 4; c++) cfr[a][b][c] = 0.f;

    auto issue = [&](int c) {
        const int k0 = c * BK;
        const uint32_t st = sb + (uint32_t)(c % NSTAGE) * STAGE_BYTES;
#pragma unroll
        for (int it = 0; it < 2; it++) {
            const int u = tid + it * 256;           // 0..511 covers 128 rows x 4 quads
            const int row = u >> 2, cq = u & 3;
            const uint32_t so = (uint32_t)(row * ROWB + cq * 16);
            const size_t gi_off = (size_t)(i0 + row) * D_DIM + k0 + cq * 8;
            const size_t gj_off = (size_t)(j0 + row) * D_DIM + k0 + cq * 8;
            cp16(st + so, g_hi + gi_off);                      // Ahi
            cp16(st + MAT_BYTES + so, g_hi + gj_off);          // Bhi
            cp16(st + 2 * MAT_BYTES + so, g_lo + gj_off);      // Blo
        }
        asm volatile("cp.async.commit_group;" ::: "memory");
    };

    issue(0);
    issue(1);
    for (int c = 0; c < NCHUNK; c++) {
        if (c < NCHUNK - 1) {
            asm volatile("cp.async.wait_group 1;" ::: "memory");
        } else {
            asm volatile("cp.async.wait_group 0;" ::: "memory");
        }
        __syncthreads();            // all warps done with buffer (c+2)%3 from iter c-1
        if (c + 2 < NCHUNK) issue(c + 2);

        const uint32_t st = sb + (uint32_t)(c % NSTAGE) * STAGE_BYTES;
        const uint32_t aHi = st, bHi = st + MAT_BYTES, bLo = st + 2 * MAT_BYTES;
        const int gl = lane >> 3;
        const uint32_t aRow = (uint32_t)(wm * 64 + (lane & 15)) * ROWB;
        const uint32_t bRow = (uint32_t)(wn * 32 + ((gl >> 1) << 3) + (lane & 7)) * ROWB;
        const uint32_t aKo = (uint32_t)((lane >> 4) << 3) * 2;
        const uint32_t bKo = (uint32_t)((gl & 1) << 3) * 2;
#pragma unroll
        for (int s = 0; s < 2; s++) {
            const uint32_t k0 = (uint32_t)(s * 16) * 2;
            uint32_t ah[4][4], bh[4][2], bl[4][2];
#pragma unroll
            for (int mt = 0; mt < 4; mt++) {
                const uint32_t ro = aRow + (uint32_t)(mt * 16) * ROWB + k0 + aKo;
                ldsm4(ah[mt][0], ah[mt][1], ah[mt][2], ah[mt][3], aHi + ro);
            }
#pragma unroll
            for (int g = 0; g < 2; g++) {
                const uint32_t ro = bRow + (uint32_t)(g * 16) * ROWB + k0 + bKo;
                ldsm4(bh[2 * g][0], bh[2 * g][1], bh[2 * g + 1][0], bh[2 * g + 1][1], bHi + ro);
                ldsm4(bl[2 * g][0], bl[2 * g][1], bl[2 * g + 1][0], bl[2 * g + 1][1], bLo + ro);
            }
#pragma unroll
            for (int mt = 0; mt < 4; mt++)
#pragma unroll
                for (int nt = 0; nt < 4; nt++) mma16816(cfr[mt][nt], ah[mt], bh[nt]);
#pragma unroll
            for (int mt = 0; mt < 4; mt++)
#pragma unroll
                for (int nt = 0; nt < 4; nt++) mma16816(cfr[mt][nt], ah[mt], bl[nt]);
        }
    }
    __syncthreads();

    // ---------------- epilogue (aliases the tile smem) ----------------
    float* sacc_i = (float*)smem;          // 1024 f
    float* sacc_j = sacc_i + 1024;         // 1024 f
    float* ssqi = sacc_j + 1024;           // 128 f
    float* ssqj = ssqi + 128;              // 128 f
    int* sti = (int*)(ssqj + 128);         // 128 i
    int* stj = sti + 128;                  // 128 i

    for (int v = tid; v < 2048; v += 256) sacc_i[v] = 0.f;
    if (tid < 128) {
        ssqi[tid] = g_sq[i0 + tid];
        sti[tid] = Tg[i0 + tid];
    } else {
        const int q = tid - 128;
        ssqj[q] = g_sq[j0 + q];
        stj[q] = Tg[j0 + q];
    }
    __syncthreads();

    const float E2 = 7.3890560989306495f;
    const float E4 = 54.598150033144236f;
    const int qrow = lane >> 2, qcol = lane & 3;

#define CELL(ILOC, JLOC, DOT, SQI, SQJ, SAME, SELF)                                  \
    {                                                                                \
        float d2 = fmaf(-2.f, (DOT), (SQI) + (SQJ));                                 \
        float dist = sqrtf(fmaxf(d2, 1e-12f));                                       \
        float tt = __expf(20.f * (1.f - dist));                                      \
        float ea = tt * tt;                                                          \
        if (SAME) {                                                                  \
            if (!(SELF)) {                                                           \
                a0 += ea; a1 += __fdividef(E4, tt); a2 += dist; a3 += 1.f;           \
            }                                                                        \
        } else {                                                                     \
            b0 += ea; b1 += E2 * tt; b2 += dist; b3 += 1.f;                          \
        }                                                                            \
    }

#define RED8(OFF)                                                 \
    {                                                             \
        a0 += __shfl_xor_sync(0xffffffffu, a0, OFF);              \
        a1 += __shfl_xor_sync(0xffffffffu, a1, OFF);              \
        a2 += __shfl_xor_sync(0xffffffffu, a2, OFF);              \
        a3 += __shfl_xor_sync(0xffffffffu, a3, OFF);              \
        b0 += __shfl_xor_sync(0xffffffffu, b0, OFF);              \
        b1 += __shfl_xor_sync(0xffffffffu, b1, OFF);              \
        b2 += __shfl_xor_sync(0xffffffffu, b2, OFF);              \
        b3 += __shfl_xor_sync(0xffffffffu, b3, OFF);              \
    }

    // i-oriented pass
#pragma unroll
    for (int mt = 0; mt < 4; mt++)
#pragma unroll
        for (int h = 0; h < 2; h++) {
            const int il = wm * 64 + mt * 16 + h * 8 + qrow;
            const float sqi = ssqi[il];
            const int ti = sti[il];
            float a0 = 0, a1 = 0, a2 = 0, a3 = 0, b0 = 0, b1 = 0, b2 = 0, b3 = 0;
#pragma unroll
            for (int nt = 0; nt < 4; nt++)
#pragma unroll
                for (int col = 0; col < 2; col++) {
                    const int jl = wn * 32 + nt * 8 + 2 * qcol + col;
                    CELL(il, jl, cfr[mt][nt][h * 2 + col], sqi, ssqj[jl],
                         (ti == stj[jl]), (diag && il == jl));
                }
            RED8(1);
            RED8(2);
            if (qcol == 0) {
                float* s = &sacc_i[il * 8];
                atomicAdd(s + 0, a0); atomicAdd(s + 1, b0);
                atomicAdd(s + 2, a1); atomicAdd(s + 3, b1);
                atomicAdd(s + 4, a2); atomicAdd(s + 5, b2);
                atomicAdd(s + 6, a3); atomicAdd(s + 7, b3);
            }
        }

    // j-oriented pass (off-diagonal tiles only; symmetric contribution)
    if (!diag) {
#pragma unroll
        for (int nt = 0; nt < 4; nt++)
#pragma unroll
            for (int col = 0; col < 2; col++) {
                const int jl = wn * 32 + nt * 8 + 2 * qcol + col;
                const float sqj = ssqj[jl];
                const int tj = stj[jl];
                float a0 = 0, a1 = 0, a2 = 0, a3 = 0, b0 = 0, b1 = 0, b2 = 0, b3 = 0;
#pragma unroll
                for (int mt = 0; mt < 4; mt++)
#pragma unroll
                    for (int h = 0; h < 2; h++) {
                        const int il = wm * 64 + mt * 16 + h * 8 + qrow;
                        CELL(il, jl, cfr[mt][nt][h * 2 + col], ssqi[il], sqj,
                             (sti[il] == tj), false);
                    }
                RED8(4);
                RED8(8);
                RED8(16);
                if (qrow == 0) {
                    float* s = &sacc_j[jl * 8];
                    atomicAdd(s + 0, a0); atomicAdd(s + 1, b0);
                    atomicAdd(s + 2, a1); atomicAdd(s + 3, b1);
                    atomicAdd(s + 4, a2); atomicAdd(s + 5, b2);
                    atomicAdd(s + 6, a3); atomicAdd(s + 7, b3);
                }
            }
    }
    __syncthreads();

    for (int v = tid; v < 1024; v += 256)
        atomicAdd(&g_acc[(size_t)(i0 + (v >> 3)) * 8 + (v & 7)], sacc_i[v]);
    if (!diag)
        for (int v = tid; v < 1024; v += 256)
            atomicAdd(&g_acc[(size_t)(j0 + (v >> 3)) * 8 + (v & 7)], sacc_j[v]);
#undef CELL
#undef RED8
}

// ---------------------------------------------------------------------------
// final: per-row loss terms + reduction -> out[4]
// ---------------------------------------------------------------------------
__global__ void final_kernel(float* __restrict__ out, int n) {
    int tid = threadIdx.x;
    float lsum = 0.f, pd = 0.f, nd = 0.f, pc = 0.f, nc = 0.f;
    for (int r = tid; r < n; r += blockDim.x) {
        const float* a = &g_acc[r * 8];
        float pl = a[0], nl = a[1], pb = a[2], nb = a[3];
        float alr = 1.f - pl / (pl + nl);
        lsum += alr * (logf(pb) + logf(nb));
        pd += a[4]; nd += a[5]; pc += a[6]; nc += a[7];
    }
    __shared__ float red[16][5];
#pragma unroll
    for (int o = 16; o > 0; o >>= 1) {
        lsum += __shfl_xor_sync(0xffffffffu, lsum, o);
        pd += __shfl_xor_sync(0xffffffffu, pd, o);
        nd += __shfl_xor_sync(0xffffffffu, nd, o);
        pc += __shfl_xor_sync(0xffffffffu, pc, o);
        nc += __shfl_xor_sync(0xffffffffu, nc, o);
    }
    int w = tid >> 5, lane = tid & 31;
    if (lane == 0) { red[w][0] = lsum; red[w][1] = pd; red[w][2] = nd; red[w][3] = pc; red[w][4] = nc; }
    __syncthreads();
    if (w == 0) {
        float v0 = (lane < 16) ? red[lane][0] : 0.f;
        float v1 = (lane < 16) ? red[lane][1] : 0.f;
        float v2 = (lane < 16) ? red[lane][2] : 0.f;
        float v3 = (lane < 16) ? red[lane][3] : 0.f;
        float v4 = (lane < 16) ? red[lane][4] : 0.f;
#pragma unroll
        for (int o = 8; o > 0; o >>= 1) {
            v0 += __shfl_xor_sync(0xffffffffu, v0, o);
            v1 += __shfl_xor_sync(0xffffffffu, v1, o);
            v2 += __shfl_xor_sync(0xffffffffu, v2, o);
            v3 += __shfl_xor_sync(0xffffffffu, v3, o);
            v4 += __shfl_xor_sync(0xffffffffu, v4, o);
        }
        if (lane == 0) {
            out[0] = v0 / (float)n;   // loss
            out[1] = 0.f;             // accuracy
            out[2] = v1 / v3;         // pos_d
            out[3] = v2 / v4;         // neg_d
        }
    }
}

// ---------------------------------------------------------------------------
extern "C" void kernel_launch(void* const* d_in, const int* in_sizes, int n_in,
                              void* d_out, int out_size) {
    const float* X = (const float*)d_in[0];
    const int* Tg = (const int*)d_in[1];
    int n = in_sizes[1];
    int d = in_sizes[0] / n;

    cudaFuncSetAttribute(pair_kernel, cudaFuncAttributeMaxDynamicSharedMemorySize, SMEM_DYN);

    prep_kernel<<<(n + 7) / 8, 256>>>(X, n, d);
    int nb = n / BT;
    int ntiles = nb * (nb + 1) / 2;
    pair_kernel<<<ntiles, 256, SMEM_DYN>>>(Tg, nb);
    final_kernel<<<1, 512>>>((float*)d_out, n);
}

// round 10
// speedup vs baseline: 7.7168x; 1.3710x over previous
#include <cuda_runtime.h>
#include <cuda_fp16.h>
#include <math.h>
#include <stdint.h>

#define N_MAX 4096
#define D_DIM 1024
#define BT 128
#define BK 32
#define STRIDE 40                              // fp16 elems per smem row (32 data + 8 pad)
#define ROWB (STRIDE * 2)                      // 80 bytes per row
#define MAT_BYTES (BT * ROWB)                  // 10240
#define STAGE_BYTES (2 * MAT_BYTES)            // A,B = 20480
#define NSTAGE 3
#define SMEM_DYN (NSTAGE * STAGE_BYTES)        // 61440
#define NCHUNK (D_DIM / BK)                    // 32

// Per-row accumulators: [0]=pos_logit [1]=neg_logit [2]=pos_beta [3]=neg_beta
//                       [4]=pos_d     [5]=neg_d     [6]=pos_cnt  [7]=neg_cnt
__device__ float g_acc[N_MAX * 8];
__device__ float g_sq[N_MAX];
__device__ __half g_h[N_MAX * D_DIM];

// ---------------------------------------------------------------------------
__device__ __forceinline__ uint32_t smem_u32(const void* p) {
    uint32_t a;
    asm("{ .reg .u64 t; cvta.to.shared.u64 t, %1; cvt.u32.u64 %0, t; }" : "=r"(a) : "l"(p));
    return a;
}
__device__ __forceinline__ void cp16(uint32_t dst, const void* src) {
    asm volatile("cp.async.cg.shared.global [%0], [%1], 16;" :: "r"(dst), "l"(src) : "memory");
}
__device__ __forceinline__ void ldsm4(uint32_t& r0, uint32_t& r1, uint32_t& r2, uint32_t& r3,
                                      uint32_t addr) {
    asm volatile("ldmatrix.sync.aligned.m8n8.x4.shared.b16 {%0,%1,%2,%3}, [%4];"
                 : "=r"(r0), "=r"(r1), "=r"(r2), "=r"(r3) : "r"(addr));
}
__device__ __forceinline__ void mma16816(float* c, const uint32_t* a, const uint32_t* b) {
    asm volatile(
        "mma.sync.aligned.m16n8k16.row.col.f32.f16.f16.f32 "
        "{%0,%1,%2,%3}, {%4,%5,%6,%7}, {%8,%9}, {%0,%1,%2,%3};"
        : "+f"(c[0]), "+f"(c[1]), "+f"(c[2]), "+f"(c[3])
        : "r"(a[0]), "r"(a[1]), "r"(a[2]), "r"(a[3]), "r"(b[0]), "r"(b[1]));
}

// ---------------------------------------------------------------------------
// prep: fp16 convert, row norms, zero accumulators. 8 rows per block,
// one warp per row, 8 independent float4 loads per lane for MLP.
// ---------------------------------------------------------------------------
__global__ void prep_kernel(const float* __restrict__ X, int n, int d) {
    const int w = threadIdx.x >> 5;
    const int lane = threadIdx.x & 31;
    const int r = blockIdx.x * 8 + w;
    if (r >= n) return;
    const float4* xr = (const float4*)(X + (size_t)r * d);

    float4 v[8];
#pragma unroll
    for (int i = 0; i < 8; i++) v[i] = xr[lane + i * 32];

    float s = 0.f;
#pragma unroll
    for (int i = 0; i < 8; i++) {
        s = fmaf(v[i].x, v[i].x, s);
        s = fmaf(v[i].y, v[i].y, s);
        s = fmaf(v[i].z, v[i].z, s);
        s = fmaf(v[i].w, v[i].w, s);
    }

#pragma unroll
    for (int i = 0; i < 8; i++) {
        __half h[4] = {__float2half(v[i].x), __float2half(v[i].y),
                       __float2half(v[i].z), __float2half(v[i].w)};
        *(ushort4*)&g_h[(size_t)r * d + (lane + i * 32) * 4] = *(ushort4*)h;
    }

#pragma unroll
    for (int o = 16; o > 0; o >>= 1) s += __shfl_xor_sync(0xffffffffu, s, o);
    if (lane == 0) g_sq[r] = s;
    if (lane < 8) g_acc[r * 8 + lane] = 0.f;
}

// ---------------------------------------------------------------------------
// pair kernel: upper-triangle 128x128 tiles, single-pass fp16 Gram.
// 3-stage cp.async ring, ONE barrier per chunk.
// ---------------------------------------------------------------------------
__global__ __launch_bounds__(256, 2) void pair_kernel(const int* __restrict__ Tg, int nb) {
    extern __shared__ __align__(16) char smem[];

    // triangular decode
    int t = blockIdx.x, bi = 0;
    while (t >= nb - bi) { t -= nb - bi; bi++; }
    const int bj = bi + t;
    const bool diag = (bi == bj);
    const int i0 = bi * BT, j0 = bj * BT;

    const int tid = threadIdx.x;
    const int lane = tid & 31;
    const int wid = tid >> 5;
    const int wm = wid & 1;        // warp row: 64 rows each
    const int wn = wid >> 1;       // warp col: 32 cols each

    const uint32_t sb = smem_u32(smem);

    float cfr[4][4][4];
#pragma unroll
    for (int a = 0; a < 4; a++)
#pragma unroll
        for (int b = 0; b < 4; b++)
#pragma unroll
            for (int c = 0; c < 4; c++) cfr[a][b][c] = 0.f;

    auto issue = [&](int c) {
        const int k0 = c * BK;
        const uint32_t st = sb + (uint32_t)(c % NSTAGE) * STAGE_BYTES;
#pragma unroll
        for (int it = 0; it < 2; it++) {
            const int u = tid + it * 256;           // 0..511 covers 128 rows x 4 quads
            const int row = u >> 2, cq = u & 3;
            const uint32_t so = (uint32_t)(row * ROWB + cq * 16);
            cp16(st + so, g_h + (size_t)(i0 + row) * D_DIM + k0 + cq * 8);              // A
            cp16(st + MAT_BYTES + so, g_h + (size_t)(j0 + row) * D_DIM + k0 + cq * 8);  // B
        }
        asm volatile("cp.async.commit_group;" ::: "memory");
    };

    issue(0);
    issue(1);
    for (int c = 0; c < NCHUNK; c++) {
        if (c < NCHUNK - 1) {
            asm volatile("cp.async.wait_group 1;" ::: "memory");
        } else {
            asm volatile("cp.async.wait_group 0;" ::: "memory");
        }
        __syncthreads();            // all warps done with buffer (c+2)%3 from iter c-1
        if (c + 2 < NCHUNK) issue(c + 2);

        const uint32_t st = sb + (uint32_t)(c % NSTAGE) * STAGE_BYTES;
        const uint32_t aB = st, bB = st + MAT_BYTES;
        const int gl = lane >> 3;
        const uint32_t aRow = (uint32_t)(wm * 64 + (lane & 15)) * ROWB;
        const uint32_t bRow = (uint32_t)(wn * 32 + ((gl >> 1) << 3) + (lane & 7)) * ROWB;
        const uint32_t aKo = (uint32_t)((lane >> 4) << 3) * 2;
        const uint32_t bKo = (uint32_t)((gl & 1) << 3) * 2;
#pragma unroll
        for (int s = 0; s < 2; s++) {
            const uint32_t k0 = (uint32_t)(s * 16) * 2;
            uint32_t af[4][4], bf[4][2];
#pragma unroll
            for (int mt = 0; mt < 4; mt++) {
                const uint32_t ro = aRow + (uint32_t)(mt * 16) * ROWB + k0 + aKo;
                ldsm4(af[mt][0], af[mt][1], af[mt][2], af[mt][3], aB + ro);
            }
#pragma unroll
            for (int g = 0; g < 2; g++) {
                const uint32_t ro = bRow + (uint32_t)(g * 16) * ROWB + k0 + bKo;
                ldsm4(bf[2 * g][0], bf[2 * g][1], bf[2 * g + 1][0], bf[2 * g + 1][1], bB + ro);
            }
#pragma unroll
            for (int mt = 0; mt < 4; mt++)
#pragma unroll
                for (int nt = 0; nt < 4; nt++) mma16816(cfr[mt][nt], af[mt], bf[nt]);
        }
    }
    __syncthreads();

    // ---------------- epilogue (aliases the tile smem) ----------------
    float* sacc_i = (float*)smem;          // 1024 f
    float* sacc_j = sacc_i + 1024;         // 1024 f
    float* ssqi = sacc_j + 1024;           // 128 f
    float* ssqj = ssqi + 128;              // 128 f
    int* sti = (int*)(ssqj + 128);         // 128 i
    int* stj = sti + 128;                  // 128 i

    for (int v = tid; v < 2048; v += 256) sacc_i[v] = 0.f;
    if (tid < 128) {
        ssqi[tid] = g_sq[i0 + tid];
        sti[tid] = Tg[i0 + tid];
    } else {
        const int q = tid - 128;
        ssqj[q] = g_sq[j0 + q];
        stj[q] = Tg[j0 + q];
    }
    __syncthreads();

    const float E2 = 7.3890560989306495f;
    const float E4 = 54.598150033144236f;
    const int qrow = lane >> 2, qcol = lane & 3;

#define CELL(ILOC, JLOC, DOT, SQI, SQJ, SAME, SELF)                                  \
    {                                                                                \
        float d2 = fmaf(-2.f, (DOT), (SQI) + (SQJ));                                 \
        float dist = sqrtf(fmaxf(d2, 1e-12f));                                       \
        float tt = __expf(20.f * (1.f - dist));                                      \
        float ea = tt * tt;                                                          \
        if (SAME) {                                                                  \
            if (!(SELF)) {                                                           \
                a0 += ea; a1 += __fdividef(E4, tt); a2 += dist; a3 += 1.f;           \
            }                                                                        \
        } else {                                                                     \
            b0 += ea; b1 += E2 * tt; b2 += dist; b3 += 1.f;                          \
        }                                                                            \
    }

#define RED8(OFF)                                                 \
    {                                                             \
        a0 += __shfl_xor_sync(0xffffffffu, a0, OFF);              \
        a1 += __shfl_xor_sync(0xffffffffu, a1, OFF);              \
        a2 += __shfl_xor_sync(0xffffffffu, a2, OFF);              \
        a3 += __shfl_xor_sync(0xffffffffu, a3, OFF);              \
        b0 += __shfl_xor_sync(0xffffffffu, b0, OFF);              \
        b1 += __shfl_xor_sync(0xffffffffu, b1, OFF);              \
        b2 += __shfl_xor_sync(0xffffffffu, b2, OFF);              \
        b3 += __shfl_xor_sync(0xffffffffu, b3, OFF);              \
    }

    // i-oriented pass
#pragma unroll
    for (int mt = 0; mt < 4; mt++)
#pragma unroll
        for (int h = 0; h < 2; h++) {
            const int il = wm * 64 + mt * 16 + h * 8 + qrow;
            const float sqi = ssqi[il];
            const int ti = sti[il];
            float a0 = 0, a1 = 0, a2 = 0, a3 = 0, b0 = 0, b1 = 0, b2 = 0, b3 = 0;
#pragma unroll
            for (int nt = 0; nt < 4; nt++)
#pragma unroll
                for (int col = 0; col < 2; col++) {
                    const int jl = wn * 32 + nt * 8 + 2 * qcol + col;
                    CELL(il, jl, cfr[mt][nt][h * 2 + col], sqi, ssqj[jl],
                         (ti == stj[jl]), (diag && il == jl));
                }
            RED8(1);
            RED8(2);
            if (qcol == 0) {
                float* s = &sacc_i[il * 8];
                atomicAdd(s + 0, a0); atomicAdd(s + 1, b0);
                atomicAdd(s + 2, a1); atomicAdd(s + 3, b1);
                atomicAdd(s + 4, a2); atomicAdd(s + 5, b2);
                atomicAdd(s + 6, a3); atomicAdd(s + 7, b3);
            }
        }

    // j-oriented pass (off-diagonal tiles only; symmetric contribution)
    if (!diag) {
#pragma unroll
        for (int nt = 0; nt < 4; nt++)
#pragma unroll
            for (int col = 0; col < 2; col++) {
                const int jl = wn * 32 + nt * 8 + 2 * qcol + col;
                const float sqj = ssqj[jl];
                const int tj = stj[jl];
                float a0 = 0, a1 = 0, a2 = 0, a3 = 0, b0 = 0, b1 = 0, b2 = 0, b3 = 0;
#pragma unroll
                for (int mt = 0; mt < 4; mt++)
#pragma unroll
                    for (int h = 0; h < 2; h++) {
                        const int il = wm * 64 + mt * 16 + h * 8 + qrow;
                        CELL(il, jl, cfr[mt][nt][h * 2 + col], ssqi[il], sqj,
                             (sti[il] == tj), false);
                    }
                RED8(4);
                RED8(8);
                RED8(16);
                if (qrow == 0) {
                    float* s = &sacc_j[jl * 8];
                    atomicAdd(s + 0, a0); atomicAdd(s + 1, b0);
                    atomicAdd(s + 2, a1); atomicAdd(s + 3, b1);
                    atomicAdd(s + 4, a2); atomicAdd(s + 5, b2);
                    atomicAdd(s + 6, a3); atomicAdd(s + 7, b3);
                }
            }
    }
    __syncthreads();

    for (int v = tid; v < 1024; v += 256)
        atomicAdd(&g_acc[(size_t)(i0 + (v >> 3)) * 8 + (v & 7)], sacc_i[v]);
    if (!diag)
        for (int v = tid; v < 1024; v += 256)
            atomicAdd(&g_acc[(size_t)(j0 + (v >> 3)) * 8 + (v & 7)], sacc_j[v]);
#undef CELL
#undef RED8
}

// ---------------------------------------------------------------------------
// final: per-row loss terms + reduction -> out[4]
// ---------------------------------------------------------------------------
__global__ void final_kernel(float* __restrict__ out, int n) {
    int tid = threadIdx.x;
    float lsum = 0.f, pd = 0.f, nd = 0.f, pc = 0.f, nc = 0.f;
    for (int r = tid; r < n; r += blockDim.x) {
        const float* a = &g_acc[r * 8];
        float pl = a[0], nl = a[1], pb = a[2], nb = a[3];
        float alr = 1.f - pl / (pl + nl);
        lsum += alr * (logf(pb) + logf(nb));
        pd += a[4]; nd += a[5]; pc += a[6]; nc += a[7];
    }
    __shared__ float red[16][5];
#pragma unroll
    for (int o = 16; o > 0; o >>= 1) {
        lsum += __shfl_xor_sync(0xffffffffu, lsum, o);
        pd += __shfl_xor_sync(0xffffffffu, pd, o);
        nd += __shfl_xor_sync(0xffffffffu, nd, o);
        pc += __shfl_xor_sync(0xffffffffu, pc, o);
        nc += __shfl_xor_sync(0xffffffffu, nc, o);
    }
    int w = tid >> 5, lane = tid & 31;
    if (lane == 0) { red[w][0] = lsum; red[w][1] = pd; red[w][2] = nd; red[w][3] = pc; red[w][4] = nc; }
    __syncthreads();
    if (w == 0) {
        float v0 = (lane < 16) ? red[lane][0] : 0.f;
        float v1 = (lane < 16) ? red[lane][1] : 0.f;
        float v2 = (lane < 16) ? red[lane][2] : 0.f;
        float v3 = (lane < 16) ? red[lane][3] : 0.f;
        float v4 = (lane < 16) ? red[lane][4] : 0.f;
#pragma unroll
        for (int o = 8; o > 0; o >>= 1) {
            v0 += __shfl_xor_sync(0xffffffffu, v0, o);
            v1 += __shfl_xor_sync(0xffffffffu, v1, o);
            v2 += __shfl_xor_sync(0xffffffffu, v2, o);
            v3 += __shfl_xor_sync(0xffffffffu, v3, o);
            v4 += __shfl_xor_sync(0xffffffffu, v4, o);
        }
        if (lane == 0) {
            out[0] = v0 / (float)n;   // loss
            out[1] = 0.f;             // accuracy
            out[2] = v1 / v3;         // pos_d
            out[3] = v2 / v4;         // neg_d
        }
    }
}

// ---------------------------------------------------------------------------
extern "C" void kernel_launch(void* const* d_in, const int* in_sizes, int n_in,
                              void* d_out, int out_size) {
    const float* X = (const float*)d_in[0];
    const int* Tg = (const int*)d_in[1];
    int n = in_sizes[1];
    int d = in_sizes[0] / n;

    cudaFuncSetAttribute(pair_kernel, cudaFuncAttributeMaxDynamicSharedMemorySize, SMEM_DYN);

    prep_kernel<<<(n + 7) / 8, 256>>>(X, n, d);
    int nb = n / BT;
    int ntiles = nb * (nb + 1) / 2;
    pair_kernel<<<ntiles, 256, SMEM_DYN>>>(Tg, nb);
    final_kernel<<<1, 512>>>((float*)d_out, n);
}